// round 15
// baseline (speedup 1.0000x reference)
#include <cuda_runtime.h>
#include <cuda_bf16.h>
#include <cstdint>

#define N_NODES 50000
#define N_EDGES 800000
#define FEATS   128
#define TILE_M  64
#define N_TILES ((N_NODES + TILE_M - 1) / TILE_M)         // 782
#define FUSED_GRID 296                                    // 2 CTAs per SM
#define EPB 2704                                          // edges per block (4-aligned)
#define SCAN_BLK 1024
#define SCAN_GRID ((N_NODES + SCAN_BLK - 1) / SCAN_BLK)   // 49

#define HIST_BLK_EDGES 1024
#define HIST_BLOCKS ((N_EDGES + HIST_BLK_EDGES - 1) / HIST_BLK_EDGES) // 782
#define WPREP_BLOCKS 8

// smem: swizzled 256-B-row bf16 tiles (no padding).
// off(r, c16) = r*256 + ((c16 ^ (r&7))<<4)  -> ldmatrix conflict-free.
#define SOFF_AHI  0
#define SOFF_ALO  16384
#define SOFF_WHI  32768
#define SOFF_WLO  65536
#define SMEM_TOTAL 98304    // 96 KB per CTA -> 2 CTAs/SM

// ---------------- device scratch (alloc-free rule: __device__ globals) -----
__device__ float g_xf[(size_t)N_NODES * FEATS];   // feat @ W^T
__device__ int   g_cnt[N_NODES];                  // per-dst degree (re-zeroed by gather)
__device__ int   g_off[N_NODES + 1];              // CSR offsets
__device__ int   g_cur[N_NODES];                  // fill cursors
__device__ int   g_bucket[N_EDGES];               // src ids bucketed by dst
__device__ int   g_part[SCAN_GRID];               // per-block totals
__device__ uint4 g_whi[FEATS * 16];               // W hi bf16, [128][128] packed
__device__ uint4 g_wlo[FEATS * 16];               // W lo bf16

// ============================ helpers ======================================
__device__ __forceinline__ uint32_t smem_u32(const void* p) {
    uint32_t a;
    asm("{ .reg .u64 t; cvta.to.shared.u64 t, %1; cvt.u32.u64 %0, t; }"
        : "=r"(a) : "l"(p));
    return a;
}
__device__ __forceinline__ uint32_t cvt_bf16x2(float hi, float lo) {
    uint32_t r;
    asm("cvt.rn.bf16x2.f32 %0, %1, %2;" : "=r"(r) : "f"(hi), "f"(lo));
    return r;
}
__device__ __forceinline__ void split8(const float4 u, const float4 v,
                                       uint4& hi, uint4& lo) {
    hi.x = cvt_bf16x2(u.y, u.x);
    hi.y = cvt_bf16x2(u.w, u.z);
    hi.z = cvt_bf16x2(v.y, v.x);
    hi.w = cvt_bf16x2(v.w, v.z);
    float h0 = __uint_as_float(hi.x << 16), h1 = __uint_as_float(hi.x & 0xFFFF0000u);
    float h2 = __uint_as_float(hi.y << 16), h3 = __uint_as_float(hi.y & 0xFFFF0000u);
    float h4 = __uint_as_float(hi.z << 16), h5 = __uint_as_float(hi.z & 0xFFFF0000u);
    float h6 = __uint_as_float(hi.w << 16), h7 = __uint_as_float(hi.w & 0xFFFF0000u);
    lo.x = cvt_bf16x2(u.y - h1, u.x - h0);
    lo.y = cvt_bf16x2(u.w - h3, u.z - h2);
    lo.z = cvt_bf16x2(v.y - h5, v.x - h4);
    lo.w = cvt_bf16x2(v.w - h7, v.z - h6);
}
__device__ __forceinline__ uint32_t swz(int r, int c16) {
    return (uint32_t)(r * 256) + (uint32_t)((c16 ^ (r & 7)) << 4);
}
#define LDSM_X4(r0, r1, r2, r3, addr)                                         \
    asm volatile("ldmatrix.sync.aligned.m8n8.x4.shared.b16 {%0,%1,%2,%3}, [%4];" \
                 : "=r"(r0), "=r"(r1), "=r"(r2), "=r"(r3) : "r"(addr))
#define MMA_BF16(d, a, b0, b1)                                                \
    asm volatile("mma.sync.aligned.m16n8k16.row.col.f32.bf16.bf16.f32 "       \
                 "{%0,%1,%2,%3}, {%4,%5,%6,%7}, {%8,%9}, {%0,%1,%2,%3};"      \
                 : "+f"(d[0]), "+f"(d[1]), "+f"(d[2]), "+f"(d[3])             \
                 : "r"(a[0]), "r"(a[1]), "r"(a[2]), "r"(a[3]), "r"(b0), "r"(b1))

// ---------------------------------------------------------------------------
// K1: histogram of dst (256 thr) + W hi/lo split (8 extra blocks).
// ---------------------------------------------------------------------------
__global__ void hist_kernel(const int* __restrict__ dst,
                            const float* __restrict__ W) {
    if (blockIdx.x < HIST_BLOCKS) {
        int e0 = blockIdx.x * HIST_BLK_EDGES + threadIdx.x * 4;
        if (e0 + 3 < N_EDGES) {
            int4 d4 = *reinterpret_cast<const int4*>(dst + e0);
            if ((unsigned)d4.x < N_NODES) atomicAdd(&g_cnt[d4.x], 1);
            if ((unsigned)d4.y < N_NODES) atomicAdd(&g_cnt[d4.y], 1);
            if ((unsigned)d4.z < N_NODES) atomicAdd(&g_cnt[d4.z], 1);
            if ((unsigned)d4.w < N_NODES) atomicAdd(&g_cnt[d4.w], 1);
        } else {
            for (int e = e0; e < N_EDGES; e++) {
                int d = dst[e];
                if ((unsigned)d < N_NODES) atomicAdd(&g_cnt[d], 1);
            }
        }
    } else {
        int g = (blockIdx.x - HIST_BLOCKS) * 256 + threadIdx.x;  // 0..2047
        int row = g >> 4, ch = g & 15;
        const float4* W4 = reinterpret_cast<const float4*>(W);
        float4 u = W4[row * 32 + ch * 2];
        float4 v = W4[row * 32 + ch * 2 + 1];
        uint4 hi, lo;
        split8(u, v, hi, lo);
        g_whi[row * 16 + ch] = hi;
        g_wlo[row * 16 + ch] = lo;
    }
}

// ---------------------------------------------------------------------------
// K2: per-block exclusive scan of g_cnt -> g_off; totals -> g_part.
// ---------------------------------------------------------------------------
__global__ void scan_local_kernel() {
    __shared__ int wsum[32];
    int tid  = threadIdx.x;
    int lane = tid & 31;
    int wid  = tid >> 5;
    int idx  = blockIdx.x * SCAN_BLK + tid;

    int x = (idx < N_NODES) ? g_cnt[idx] : 0;

    int v = x;
    #pragma unroll
    for (int d = 1; d < 32; d <<= 1) {
        int t = __shfl_up_sync(0xffffffff, v, d);
        if (lane >= d) v += t;
    }
    if (lane == 31) wsum[wid] = v;
    __syncthreads();
    if (wid == 0) {
        int w = wsum[lane];
        #pragma unroll
        for (int d = 1; d < 32; d <<= 1) {
            int t = __shfl_up_sync(0xffffffff, w, d);
            if (lane >= d) w += t;
        }
        wsum[lane] = w;
    }
    __syncthreads();

    int excl = v - x + ((wid > 0) ? wsum[wid - 1] : 0);
    if (idx < N_NODES) g_off[idx] = excl;
    if (tid == SCAN_BLK - 1) g_part[blockIdx.x] = excl + x;
}

// ---------------------------------------------------------------------------
// K3: add block offsets; copy to cursors; sentinel.
// ---------------------------------------------------------------------------
__global__ void scan_add_kernel() {
    __shared__ int s_off;
    int tid = threadIdx.x;
    if (tid < 32) {
        int v = 0;
        for (int j = tid; j < blockIdx.x; j += 32) v += g_part[j];
        #pragma unroll
        for (int d = 16; d > 0; d >>= 1) v += __shfl_down_sync(0xffffffff, v, d);
        if (tid == 0) s_off = v;
    }
    __syncthreads();

    int idx = blockIdx.x * SCAN_BLK + tid;
    if (idx < N_NODES) {
        int o = g_off[idx] + s_off;
        g_off[idx] = o;
        g_cur[idx] = o;
    }
    if (blockIdx.x == 0 && tid == 0) g_off[N_NODES] = N_EDGES;
}

// ---------------------------------------------------------------------------
// K4: PERSISTENT fused fill + HMMA GEMM. Grid = 296 (2 CTAs/SM -> 32 warps).
//   Each block: (a) fills its 2704-edge slice, (b) stages W hi/lo ONCE,
//   (c) loops 64-row A-tiles t = b, b+296, ...
// Warp layout per CTA: 16 warps = 2 row-pairs (32 rows) x 8 col-groups
// (16 cols). Two m-tiles processed sequentially per k-step to cap registers.
// Chains: Ahi*Whi + Ahi*Wlo + Alo*Whi, fp32 acc.
// ---------------------------------------------------------------------------
__global__ void __launch_bounds__(512, 2)
fused_kernel(const int* __restrict__ src,
             const int* __restrict__ dst,
             const float* __restrict__ A)   // feat [N,128]
{
    extern __shared__ char smc[];
    const uint32_t sb = smem_u32(smc);
    const int tid  = threadIdx.x;
    const int lane = tid & 31;
    const int wid  = tid >> 5;                  // 0..15
    const int b    = blockIdx.x;

    // ---- (a) fill slice: edges [b*EPB, (b+1)*EPB) ----
    {
        int base = b * EPB;
        int lim  = base + EPB;
        #pragma unroll
        for (int it = 0; it < 2; it++) {
            int e0 = base + it * 2048 + tid * 4;
            if (e0 < lim) {
                if (e0 + 3 < N_EDGES) {
                    int4 s4 = *reinterpret_cast<const int4*>(src + e0);
                    int4 d4 = *reinterpret_cast<const int4*>(dst + e0);
                    int p0 = ((unsigned)d4.x < N_NODES) ? atomicAdd(&g_cur[d4.x], 1) : -1;
                    int p1 = ((unsigned)d4.y < N_NODES) ? atomicAdd(&g_cur[d4.y], 1) : -1;
                    int p2 = ((unsigned)d4.z < N_NODES) ? atomicAdd(&g_cur[d4.z], 1) : -1;
                    int p3 = ((unsigned)d4.w < N_NODES) ? atomicAdd(&g_cur[d4.w], 1) : -1;
                    if (p0 >= 0 && (unsigned)s4.x < N_NODES) g_bucket[p0] = s4.x;
                    if (p1 >= 0 && (unsigned)s4.y < N_NODES) g_bucket[p1] = s4.y;
                    if (p2 >= 0 && (unsigned)s4.z < N_NODES) g_bucket[p2] = s4.z;
                    if (p3 >= 0 && (unsigned)s4.w < N_NODES) g_bucket[p3] = s4.w;
                } else {
                    for (int e = e0; e < N_EDGES && e < e0 + 4; e++) {
                        int d = dst[e], s = src[e];
                        if ((unsigned)d < N_NODES && (unsigned)s < N_NODES) {
                            int pos = atomicAdd(&g_cur[d], 1);
                            g_bucket[pos] = s;
                        }
                    }
                }
            }
        }
    }

    // ---- (b) stage W hi/lo ONCE (swizzled) ----
    {
        #pragma unroll
        for (int t = 0; t < 4; t++) {
            int i = tid + t * 512;          // 0..2047
            int r = i >> 4, g = i & 15;
            uint32_t off = swz(r, g);
            *reinterpret_cast<uint4*>(smc + SOFF_WHI + off) = g_whi[i];
            *reinterpret_cast<uint4*>(smc + SOFF_WLO + off) = g_wlo[i];
        }
    }

    // warp geometry (loop-invariant)
    const int mt2 = wid & 1;                // row pair: rows mt2*32 .. +31
    const int ch  = wid >> 1;               // col group (16 cols)
    const int lrow  = lane & 15;
    const int khalf = lane >> 4;
    const int rA = mt2 * 32 + lrow;
    const int rB = rA + 16;
    const uint32_t rAbase = (uint32_t)(rA * 256);
    const uint32_t rBbase = (uint32_t)(rB * 256);
    const uint32_t rm = (uint32_t)(lrow & 7);      // rA&7 == rB&7
    const int lr = lane & 7, q = lane >> 3;
    const int wrow = ch * 16 + lr + ((q >> 1) << 3);
    const int wk = q & 1;
    const uint32_t wrbase = (uint32_t)(wrow * 256);
    const uint32_t wrm = (uint32_t)(wrow & 7);

    const float4* A4 = reinterpret_cast<const float4*>(A);

    // ---- (c) persistent A-tile loop ----
    for (int t = b; t < N_TILES; t += FUSED_GRID) {
        const int row0 = t * TILE_M;
        __syncthreads();   // W ready (first iter); prior k-loop done (later iters)

        // stage A hi/lo: 64 rows x 16 chunks (swizzled), 2 items/thread
        #pragma unroll
        for (int u = 0; u < 2; u++) {
            int i = tid + u * 512;          // 0..1023
            int r = i >> 4, g = i & 15;
            int row = row0 + r;
            float4 x, y;
            if (row < N_NODES) {
                x = A4[(size_t)row * 32 + g * 2];
                y = A4[(size_t)row * 32 + g * 2 + 1];
            } else {
                x = make_float4(0.f, 0.f, 0.f, 0.f);
                y = x;
            }
            uint4 hi, lo;
            split8(x, y, hi, lo);
            uint32_t off = swz(r, g);
            *reinterpret_cast<uint4*>(smc + SOFF_AHI + off) = hi;
            *reinterpret_cast<uint4*>(smc + SOFF_ALO + off) = lo;
        }
        __syncthreads();

        float acc[4][4];   // [mA-n0, mA-n1, mB-n0, mB-n1]
        #pragma unroll
        for (int nt = 0; nt < 4; nt++)
            #pragma unroll
            for (int c = 0; c < 4; c++) acc[nt][c] = 0.f;

        #pragma unroll
        for (int ks = 0; ks < 8; ks++) {
            const int c16a = ks * 2 + khalf;
            const int c16w = ks * 2 + wk;
            uint32_t woff = wrbase + (((uint32_t)c16w ^ wrm) << 4);
            uint32_t bh[4], bl[4];
            LDSM_X4(bh[0], bh[1], bh[2], bh[3], sb + SOFF_WHI + woff);
            LDSM_X4(bl[0], bl[1], bl[2], bl[3], sb + SOFF_WLO + woff);

            uint32_t ah[4], al[4];
            uint32_t aAoff = rAbase + (((uint32_t)c16a ^ rm) << 4);
            LDSM_X4(ah[0], ah[1], ah[2], ah[3], sb + SOFF_AHI + aAoff);
            LDSM_X4(al[0], al[1], al[2], al[3], sb + SOFF_ALO + aAoff);
            MMA_BF16(acc[0], ah, bh[0], bh[1]);
            MMA_BF16(acc[0], ah, bl[0], bl[1]);
            MMA_BF16(acc[0], al, bh[0], bh[1]);
            MMA_BF16(acc[1], ah, bh[2], bh[3]);
            MMA_BF16(acc[1], ah, bl[2], bl[3]);
            MMA_BF16(acc[1], al, bh[2], bh[3]);

            uint32_t aBoff = rBbase + (((uint32_t)c16a ^ rm) << 4);
            LDSM_X4(ah[0], ah[1], ah[2], ah[3], sb + SOFF_AHI + aBoff);
            LDSM_X4(al[0], al[1], al[2], al[3], sb + SOFF_ALO + aBoff);
            MMA_BF16(acc[2], ah, bh[0], bh[1]);
            MMA_BF16(acc[2], ah, bl[0], bl[1]);
            MMA_BF16(acc[2], al, bh[0], bh[1]);
            MMA_BF16(acc[3], ah, bh[2], bh[3]);
            MMA_BF16(acc[3], ah, bl[2], bl[3]);
            MMA_BF16(acc[3], al, bh[2], bh[3]);
        }

        // epilogue: warp covers rows [mt2*32, +32), cols [ch*16, +16)
        {
            int c0 = ch * 16 + 2 * (lane & 3);
            int r0 = row0 + mt2 * 32 + (lane >> 2);
            #pragma unroll
            for (int nt = 0; nt < 2; nt++) {
                int col = c0 + nt * 8;
                if (r0 < N_NODES)
                    *reinterpret_cast<float2*>(&g_xf[(size_t)r0 * FEATS + col]) =
                        make_float2(acc[nt][0], acc[nt][1]);
                if (r0 + 8 < N_NODES)
                    *reinterpret_cast<float2*>(&g_xf[(size_t)(r0 + 8) * FEATS + col]) =
                        make_float2(acc[nt][2], acc[nt][3]);
                if (r0 + 16 < N_NODES)
                    *reinterpret_cast<float2*>(&g_xf[(size_t)(r0 + 16) * FEATS + col]) =
                        make_float2(acc[nt + 2][0], acc[nt + 2][1]);
                if (r0 + 24 < N_NODES)
                    *reinterpret_cast<float2*>(&g_xf[(size_t)(r0 + 24) * FEATS + col]) =
                        make_float2(acc[nt + 2][2], acc[nt + 2][3]);
            }
        }
    }
}

// ---------------------------------------------------------------------------
// K5: out[d] = relu( sum_{s in nbrs(d)} xf[s] + bias ). Warp per node.
// Re-zeroes g_cnt for the next replay.
// ---------------------------------------------------------------------------
__global__ void gather_bias_relu_kernel(const float* __restrict__ bias,
                                        float* __restrict__ out) {
    int gtid = blockIdx.x * blockDim.x + threadIdx.x;
    if (gtid < N_NODES) g_cnt[gtid] = 0;

    int node = gtid >> 5;
    int lane = threadIdx.x & 31;
    if (node >= N_NODES) return;

    int beg = g_off[node];
    int end = g_off[node + 1];

    float4 acc = reinterpret_cast<const float4*>(bias)[lane];
    const float4* xf4 = reinterpret_cast<const float4*>(g_xf);

    int i = beg;
    for (; i + 4 <= end; i += 4) {
        int s0 = g_bucket[i + 0];
        int s1 = g_bucket[i + 1];
        int s2 = g_bucket[i + 2];
        int s3 = g_bucket[i + 3];
        float4 v0 = xf4[(size_t)s0 * 32 + lane];
        float4 v1 = xf4[(size_t)s1 * 32 + lane];
        float4 v2 = xf4[(size_t)s2 * 32 + lane];
        float4 v3 = xf4[(size_t)s3 * 32 + lane];
        acc.x += (v0.x + v1.x) + (v2.x + v3.x);
        acc.y += (v0.y + v1.y) + (v2.y + v3.y);
        acc.z += (v0.z + v1.z) + (v2.z + v3.z);
        acc.w += (v0.w + v1.w) + (v2.w + v3.w);
    }
    for (; i < end; i++) {
        int s = g_bucket[i];
        float4 v = xf4[(size_t)s * 32 + lane];
        acc.x += v.x; acc.y += v.y; acc.z += v.z; acc.w += v.w;
    }

    float4 r;
    r.x = fmaxf(acc.x, 0.f);
    r.y = fmaxf(acc.y, 0.f);
    r.z = fmaxf(acc.z, 0.f);
    r.w = fmaxf(acc.w, 0.f);
    reinterpret_cast<float4*>(out)[(size_t)node * 32 + lane] = r;
}

// ---------------------------------------------------------------------------
extern "C" void kernel_launch(void* const* d_in, const int* in_sizes, int n_in,
                              void* d_out, int out_size) {
    const float* feat = (const float*)d_in[0];   // [50000,128] f32
    const int*   src  = (const int*)d_in[1];     // [800000] i32
    const int*   dst  = (const int*)d_in[2];     // [800000] i32
    const float* W    = (const float*)d_in[3];   // [128,128] f32
    const float* bias = (const float*)d_in[4];   // [128] f32
    float*       out  = (float*)d_out;           // [50000,128] f32

    (void)in_sizes; (void)n_in; (void)out_size;

    cudaFuncSetAttribute(fused_kernel,
                         cudaFuncAttributeMaxDynamicSharedMemorySize, SMEM_TOTAL);

    hist_kernel<<<HIST_BLOCKS + WPREP_BLOCKS, 256>>>(dst, W);
    scan_local_kernel<<<SCAN_GRID, SCAN_BLK>>>();
    scan_add_kernel<<<SCAN_GRID, SCAN_BLK>>>();
    fused_kernel<<<FUSED_GRID, 512, SMEM_TOTAL>>>(src, dst, feat);

    {
        long long threads = (long long)N_NODES * 32;
        int blocks = (int)((threads + 255) / 256);
        gather_bias_relu_kernel<<<blocks, 256>>>(bias, out);
    }
}

// round 16
// speedup vs baseline: 1.0286x; 1.0286x over previous
#include <cuda_runtime.h>
#include <cuda_bf16.h>
#include <cstdint>

#define N_NODES 50000
#define N_EDGES 800000
#define FEATS   128
#define TILE_M  64
#define N_TILES ((N_NODES + TILE_M - 1) / TILE_M)         // 782
#define FUSED_GRID 296                                    // 2 CTAs per SM
#define EPB 2704                                          // edges per block (4-aligned)
#define SCAN_BLK 1024
#define SCAN_GRID ((N_NODES + SCAN_BLK - 1) / SCAN_BLK)   // 49

#define HIST_BLK_EDGES 1024
#define HIST_BLOCKS ((N_EDGES + HIST_BLK_EDGES - 1) / HIST_BLK_EDGES) // 782
#define WPREP_BLOCKS 8

// smem: swizzled 256-B-row bf16 tiles (no padding).
// off(r, c16) = r*256 + ((c16 ^ (r&7))<<4)  -> ldmatrix conflict-free.
#define SOFF_AHI  0
#define SOFF_ALO  16384
#define SOFF_WHI  32768
#define SOFF_WLO  65536
#define SMEM_TOTAL 98304    // 96 KB per CTA -> 2 CTAs/SM

// ---------------- device scratch (alloc-free rule: __device__ globals) -----
__device__ float g_xf[(size_t)N_NODES * FEATS];   // feat @ W^T
__device__ int   g_cnt[N_NODES];                  // per-dst degree (re-zeroed by gather)
__device__ int   g_off[N_NODES + 1];              // CSR offsets
__device__ int   g_cur[N_NODES];                  // fill cursors
__device__ int   g_bucket[N_EDGES];               // src ids bucketed by dst
__device__ int   g_part[SCAN_GRID];               // per-block totals
__device__ uint4 g_whi[FEATS * 16];               // W hi bf16, [128][128] packed
__device__ uint4 g_wlo[FEATS * 16];               // W lo bf16

// ============================ helpers ======================================
__device__ __forceinline__ uint32_t smem_u32(const void* p) {
    uint32_t a;
    asm("{ .reg .u64 t; cvta.to.shared.u64 t, %1; cvt.u32.u64 %0, t; }"
        : "=r"(a) : "l"(p));
    return a;
}
__device__ __forceinline__ uint32_t cvt_bf16x2(float hi, float lo) {
    uint32_t r;
    asm("cvt.rn.bf16x2.f32 %0, %1, %2;" : "=r"(r) : "f"(hi), "f"(lo));
    return r;
}
__device__ __forceinline__ void split8(const float4 u, const float4 v,
                                       uint4& hi, uint4& lo) {
    hi.x = cvt_bf16x2(u.y, u.x);
    hi.y = cvt_bf16x2(u.w, u.z);
    hi.z = cvt_bf16x2(v.y, v.x);
    hi.w = cvt_bf16x2(v.w, v.z);
    float h0 = __uint_as_float(hi.x << 16), h1 = __uint_as_float(hi.x & 0xFFFF0000u);
    float h2 = __uint_as_float(hi.y << 16), h3 = __uint_as_float(hi.y & 0xFFFF0000u);
    float h4 = __uint_as_float(hi.z << 16), h5 = __uint_as_float(hi.z & 0xFFFF0000u);
    float h6 = __uint_as_float(hi.w << 16), h7 = __uint_as_float(hi.w & 0xFFFF0000u);
    lo.x = cvt_bf16x2(u.y - h1, u.x - h0);
    lo.y = cvt_bf16x2(u.w - h3, u.z - h2);
    lo.z = cvt_bf16x2(v.y - h5, v.x - h4);
    lo.w = cvt_bf16x2(v.w - h7, v.z - h6);
}
__device__ __forceinline__ uint32_t swz(int r, int c16) {
    return (uint32_t)(r * 256) + (uint32_t)((c16 ^ (r & 7)) << 4);
}
#define LDSM_X4(r0, r1, r2, r3, addr)                                         \
    asm volatile("ldmatrix.sync.aligned.m8n8.x4.shared.b16 {%0,%1,%2,%3}, [%4];" \
                 : "=r"(r0), "=r"(r1), "=r"(r2), "=r"(r3) : "r"(addr))
#define MMA_BF16(d, a, b0, b1)                                                \
    asm volatile("mma.sync.aligned.m16n8k16.row.col.f32.bf16.bf16.f32 "       \
                 "{%0,%1,%2,%3}, {%4,%5,%6,%7}, {%8,%9}, {%0,%1,%2,%3};"      \
                 : "+f"(d[0]), "+f"(d[1]), "+f"(d[2]), "+f"(d[3])             \
                 : "r"(a[0]), "r"(a[1]), "r"(a[2]), "r"(a[3]), "r"(b0), "r"(b1))

// ---------------------------------------------------------------------------
// K1: histogram of dst (256 thr) + W hi/lo split (8 extra blocks).
// ---------------------------------------------------------------------------
__global__ void hist_kernel(const int* __restrict__ dst,
                            const float* __restrict__ W) {
    if (blockIdx.x < HIST_BLOCKS) {
        int e0 = blockIdx.x * HIST_BLK_EDGES + threadIdx.x * 4;
        if (e0 + 3 < N_EDGES) {
            int4 d4 = *reinterpret_cast<const int4*>(dst + e0);
            if ((unsigned)d4.x < N_NODES) atomicAdd(&g_cnt[d4.x], 1);
            if ((unsigned)d4.y < N_NODES) atomicAdd(&g_cnt[d4.y], 1);
            if ((unsigned)d4.z < N_NODES) atomicAdd(&g_cnt[d4.z], 1);
            if ((unsigned)d4.w < N_NODES) atomicAdd(&g_cnt[d4.w], 1);
        } else {
            for (int e = e0; e < N_EDGES; e++) {
                int d = dst[e];
                if ((unsigned)d < N_NODES) atomicAdd(&g_cnt[d], 1);
            }
        }
    } else {
        int g = (blockIdx.x - HIST_BLOCKS) * 256 + threadIdx.x;  // 0..2047
        int row = g >> 4, ch = g & 15;
        const float4* W4 = reinterpret_cast<const float4*>(W);
        float4 u = W4[row * 32 + ch * 2];
        float4 v = W4[row * 32 + ch * 2 + 1];
        uint4 hi, lo;
        split8(u, v, hi, lo);
        g_whi[row * 16 + ch] = hi;
        g_wlo[row * 16 + ch] = lo;
    }
}

// ---------------------------------------------------------------------------
// K2: per-block exclusive scan of g_cnt -> g_off; totals -> g_part.
// ---------------------------------------------------------------------------
__global__ void scan_local_kernel() {
    __shared__ int wsum[32];
    int tid  = threadIdx.x;
    int lane = tid & 31;
    int wid  = tid >> 5;
    int idx  = blockIdx.x * SCAN_BLK + tid;

    int x = (idx < N_NODES) ? g_cnt[idx] : 0;

    int v = x;
    #pragma unroll
    for (int d = 1; d < 32; d <<= 1) {
        int t = __shfl_up_sync(0xffffffff, v, d);
        if (lane >= d) v += t;
    }
    if (lane == 31) wsum[wid] = v;
    __syncthreads();
    if (wid == 0) {
        int w = wsum[lane];
        #pragma unroll
        for (int d = 1; d < 32; d <<= 1) {
            int t = __shfl_up_sync(0xffffffff, w, d);
            if (lane >= d) w += t;
        }
        wsum[lane] = w;
    }
    __syncthreads();

    int excl = v - x + ((wid > 0) ? wsum[wid - 1] : 0);
    if (idx < N_NODES) g_off[idx] = excl;
    if (tid == SCAN_BLK - 1) g_part[blockIdx.x] = excl + x;
}

// ---------------------------------------------------------------------------
// K3: add block offsets; copy to cursors; sentinel.
// ---------------------------------------------------------------------------
__global__ void scan_add_kernel() {
    __shared__ int s_off;
    int tid = threadIdx.x;
    if (tid < 32) {
        int v = 0;
        for (int j = tid; j < blockIdx.x; j += 32) v += g_part[j];
        #pragma unroll
        for (int d = 16; d > 0; d >>= 1) v += __shfl_down_sync(0xffffffff, v, d);
        if (tid == 0) s_off = v;
    }
    __syncthreads();

    int idx = blockIdx.x * SCAN_BLK + tid;
    if (idx < N_NODES) {
        int o = g_off[idx] + s_off;
        g_off[idx] = o;
        g_cur[idx] = o;
    }
    if (blockIdx.x == 0 && tid == 0) g_off[N_NODES] = N_EDGES;
}

// ---------------------------------------------------------------------------
// K4: PERSISTENT fused fill + HMMA GEMM. Grid = 296, 256 thr, 2 CTAs/SM.
//   Each block: (a) fills its 2704-edge slice, (b) stages W hi/lo ONCE,
//   (c) loops 64-row A-tiles t = b, b+296, ...
// Warp tile: 8 warps = 2 row-pairs (32 rows) x 4 col-groups (32 cols).
// Per k-step: 4 A-LDSM + 4 W-LDSM -> 24 MMAs (ratio 3.0, was 2.0).
// Chains: Ahi*Whi + Ahi*Wlo + Alo*Whi, fp32 acc.
// ---------------------------------------------------------------------------
__global__ void __launch_bounds__(256, 2)
fused_kernel(const int* __restrict__ src,
             const int* __restrict__ dst,
             const float* __restrict__ A)   // feat [N,128]
{
    extern __shared__ char smc[];
    const uint32_t sb = smem_u32(smc);
    const int tid  = threadIdx.x;
    const int lane = tid & 31;
    const int wid  = tid >> 5;                  // 0..7
    const int b    = blockIdx.x;

    // ---- (a) fill slice: edges [b*EPB, (b+1)*EPB) ----
    {
        int base = b * EPB;
        int lim  = base + EPB;
        #pragma unroll
        for (int it = 0; it < 3; it++) {
            int e0 = base + it * 1024 + tid * 4;
            if (e0 < lim) {
                if (e0 + 3 < N_EDGES) {
                    int4 s4 = *reinterpret_cast<const int4*>(src + e0);
                    int4 d4 = *reinterpret_cast<const int4*>(dst + e0);
                    int p0 = ((unsigned)d4.x < N_NODES) ? atomicAdd(&g_cur[d4.x], 1) : -1;
                    int p1 = ((unsigned)d4.y < N_NODES) ? atomicAdd(&g_cur[d4.y], 1) : -1;
                    int p2 = ((unsigned)d4.z < N_NODES) ? atomicAdd(&g_cur[d4.z], 1) : -1;
                    int p3 = ((unsigned)d4.w < N_NODES) ? atomicAdd(&g_cur[d4.w], 1) : -1;
                    if (p0 >= 0 && (unsigned)s4.x < N_NODES) g_bucket[p0] = s4.x;
                    if (p1 >= 0 && (unsigned)s4.y < N_NODES) g_bucket[p1] = s4.y;
                    if (p2 >= 0 && (unsigned)s4.z < N_NODES) g_bucket[p2] = s4.z;
                    if (p3 >= 0 && (unsigned)s4.w < N_NODES) g_bucket[p3] = s4.w;
                } else {
                    for (int e = e0; e < N_EDGES && e < e0 + 4; e++) {
                        int d = dst[e], s = src[e];
                        if ((unsigned)d < N_NODES && (unsigned)s < N_NODES) {
                            int pos = atomicAdd(&g_cur[d], 1);
                            g_bucket[pos] = s;
                        }
                    }
                }
            }
        }
    }

    // ---- (b) stage W hi/lo ONCE (swizzled) ----
    {
        #pragma unroll
        for (int t = 0; t < 8; t++) {
            int i = tid + t * 256;          // 0..2047
            int r = i >> 4, g = i & 15;
            uint32_t off = swz(r, g);
            *reinterpret_cast<uint4*>(smc + SOFF_WHI + off) = g_whi[i];
            *reinterpret_cast<uint4*>(smc + SOFF_WLO + off) = g_wlo[i];
        }
    }

    // warp geometry (loop-invariant)
    const int mp = wid & 1;                 // row pair: rows mp*32 .. +31
    const int ch = wid >> 1;                // col group (32 cols = 4 n-tiles)
    const int lrow  = lane & 15;
    const int khalf = lane >> 4;
    const int rA = mp * 32 + lrow;          // m-tile A rows
    const int rB = rA + 16;                 // m-tile B rows
    const uint32_t rAbase = (uint32_t)(rA * 256);
    const uint32_t rBbase = (uint32_t)(rB * 256);
    const uint32_t rm = (uint32_t)(lrow & 7);
    const int lr = lane & 7, q = lane >> 3;
    const int wrl = lr + ((q >> 1) << 3);   // 0..15 within an n-tile pair
    const int wk = q & 1;
    const int wrow0 = ch * 32 + wrl;        // n-pair 0 (n-tiles 0,1)
    const int wrow1 = ch * 32 + 16 + wrl;   // n-pair 1 (n-tiles 2,3)
    const uint32_t w0base = (uint32_t)(wrow0 * 256), w0m = (uint32_t)(wrow0 & 7);
    const uint32_t w1base = (uint32_t)(wrow1 * 256), w1m = (uint32_t)(wrow1 & 7);

    const float4* A4 = reinterpret_cast<const float4*>(A);

    // ---- (c) persistent A-tile loop ----
    for (int t = b; t < N_TILES; t += FUSED_GRID) {
        const int row0 = t * TILE_M;
        __syncthreads();   // W ready (first iter); prior k-loop done (later iters)

        // stage A hi/lo: 64 rows x 16 chunks (swizzled), 4 items/thread
        #pragma unroll
        for (int u = 0; u < 4; u++) {
            int i = tid + u * 256;          // 0..1023
            int r = i >> 4, g = i & 15;
            int row = row0 + r;
            float4 x, y;
            if (row < N_NODES) {
                x = A4[(size_t)row * 32 + g * 2];
                y = A4[(size_t)row * 32 + g * 2 + 1];
            } else {
                x = make_float4(0.f, 0.f, 0.f, 0.f);
                y = x;
            }
            uint4 hi, lo;
            split8(x, y, hi, lo);
            uint32_t off = swz(r, g);
            *reinterpret_cast<uint4*>(smc + SOFF_AHI + off) = hi;
            *reinterpret_cast<uint4*>(smc + SOFF_ALO + off) = lo;
        }
        __syncthreads();

        float accA[4][4], accB[4][4];   // [n-tile][frag] for m-tiles A and B
        #pragma unroll
        for (int nt = 0; nt < 4; nt++)
            #pragma unroll
            for (int c = 0; c < 4; c++) { accA[nt][c] = 0.f; accB[nt][c] = 0.f; }

        #pragma unroll
        for (int ks = 0; ks < 8; ks++) {
            const int c16a = ks * 2 + khalf;
            const int c16w = ks * 2 + wk;

            uint32_t bh0[4], bl0[4], bh1[4], bl1[4];
            uint32_t w0off = w0base + (((uint32_t)c16w ^ w0m) << 4);
            uint32_t w1off = w1base + (((uint32_t)c16w ^ w1m) << 4);
            LDSM_X4(bh0[0], bh0[1], bh0[2], bh0[3], sb + SOFF_WHI + w0off);
            LDSM_X4(bl0[0], bl0[1], bl0[2], bl0[3], sb + SOFF_WLO + w0off);
            LDSM_X4(bh1[0], bh1[1], bh1[2], bh1[3], sb + SOFF_WHI + w1off);
            LDSM_X4(bl1[0], bl1[1], bl1[2], bl1[3], sb + SOFF_WLO + w1off);

            uint32_t ahA[4], alA[4], ahB[4], alB[4];
            uint32_t aAoff = rAbase + (((uint32_t)c16a ^ rm) << 4);
            uint32_t aBoff = rBbase + (((uint32_t)c16a ^ rm) << 4);
            LDSM_X4(ahA[0], ahA[1], ahA[2], ahA[3], sb + SOFF_AHI + aAoff);
            LDSM_X4(alA[0], alA[1], alA[2], alA[3], sb + SOFF_ALO + aAoff);
            LDSM_X4(ahB[0], ahB[1], ahB[2], ahB[3], sb + SOFF_AHI + aBoff);
            LDSM_X4(alB[0], alB[1], alB[2], alB[3], sb + SOFF_ALO + aBoff);

            // m-tile A
            MMA_BF16(accA[0], ahA, bh0[0], bh0[1]);
            MMA_BF16(accA[0], ahA, bl0[0], bl0[1]);
            MMA_BF16(accA[0], alA, bh0[0], bh0[1]);
            MMA_BF16(accA[1], ahA, bh0[2], bh0[3]);
            MMA_BF16(accA[1], ahA, bl0[2], bl0[3]);
            MMA_BF16(accA[1], alA, bh0[2], bh0[3]);
            MMA_BF16(accA[2], ahA, bh1[0], bh1[1]);
            MMA_BF16(accA[2], ahA, bl1[0], bl1[1]);
            MMA_BF16(accA[2], alA, bh1[0], bh1[1]);
            MMA_BF16(accA[3], ahA, bh1[2], bh1[3]);
            MMA_BF16(accA[3], ahA, bl1[2], bl1[3]);
            MMA_BF16(accA[3], alA, bh1[2], bh1[3]);
            // m-tile B
            MMA_BF16(accB[0], ahB, bh0[0], bh0[1]);
            MMA_BF16(accB[0], ahB, bl0[0], bl0[1]);
            MMA_BF16(accB[0], alB, bh0[0], bh0[1]);
            MMA_BF16(accB[1], ahB, bh0[2], bh0[3]);
            MMA_BF16(accB[1], ahB, bl0[2], bl0[3]);
            MMA_BF16(accB[1], alB, bh0[2], bh0[3]);
            MMA_BF16(accB[2], ahB, bh1[0], bh1[1]);
            MMA_BF16(accB[2], ahB, bl1[0], bl1[1]);
            MMA_BF16(accB[2], alB, bh1[0], bh1[1]);
            MMA_BF16(accB[3], ahB, bh1[2], bh1[3]);
            MMA_BF16(accB[3], ahB, bl1[2], bl1[3]);
            MMA_BF16(accB[3], alB, bh1[2], bh1[3]);
        }

        // epilogue: warp covers rows [mp*32, +32), cols [ch*32, +32)
        {
            int c0 = ch * 32 + 2 * (lane & 3);
            int r0 = row0 + mp * 32 + (lane >> 2);
            #pragma unroll
            for (int nt = 0; nt < 4; nt++) {
                int col = c0 + nt * 8;
                if (r0 < N_NODES)
                    *reinterpret_cast<float2*>(&g_xf[(size_t)r0 * FEATS + col]) =
                        make_float2(accA[nt][0], accA[nt][1]);
                if (r0 + 8 < N_NODES)
                    *reinterpret_cast<float2*>(&g_xf[(size_t)(r0 + 8) * FEATS + col]) =
                        make_float2(accA[nt][2], accA[nt][3]);
                if (r0 + 16 < N_NODES)
                    *reinterpret_cast<float2*>(&g_xf[(size_t)(r0 + 16) * FEATS + col]) =
                        make_float2(accB[nt][0], accB[nt][1]);
                if (r0 + 24 < N_NODES)
                    *reinterpret_cast<float2*>(&g_xf[(size_t)(r0 + 24) * FEATS + col]) =
                        make_float2(accB[nt][2], accB[nt][3]);
            }
        }
    }
}

// ---------------------------------------------------------------------------
// K5: out[d] = relu( sum_{s in nbrs(d)} xf[s] + bias ). Warp per node.
// Re-zeroes g_cnt for the next replay.
// ---------------------------------------------------------------------------
__global__ void gather_bias_relu_kernel(const float* __restrict__ bias,
                                        float* __restrict__ out) {
    int gtid = blockIdx.x * blockDim.x + threadIdx.x;
    if (gtid < N_NODES) g_cnt[gtid] = 0;

    int node = gtid >> 5;
    int lane = threadIdx.x & 31;
    if (node >= N_NODES) return;

    int beg = g_off[node];
    int end = g_off[node + 1];

    float4 acc = reinterpret_cast<const float4*>(bias)[lane];
    const float4* xf4 = reinterpret_cast<const float4*>(g_xf);

    int i = beg;
    for (; i + 4 <= end; i += 4) {
        int s0 = g_bucket[i + 0];
        int s1 = g_bucket[i + 1];
        int s2 = g_bucket[i + 2];
        int s3 = g_bucket[i + 3];
        float4 v0 = xf4[(size_t)s0 * 32 + lane];
        float4 v1 = xf4[(size_t)s1 * 32 + lane];
        float4 v2 = xf4[(size_t)s2 * 32 + lane];
        float4 v3 = xf4[(size_t)s3 * 32 + lane];
        acc.x += (v0.x + v1.x) + (v2.x + v3.x);
        acc.y += (v0.y + v1.y) + (v2.y + v3.y);
        acc.z += (v0.z + v1.z) + (v2.z + v3.z);
        acc.w += (v0.w + v1.w) + (v2.w + v3.w);
    }
    for (; i < end; i++) {
        int s = g_bucket[i];
        float4 v = xf4[(size_t)s * 32 + lane];
        acc.x += v.x; acc.y += v.y; acc.z += v.z; acc.w += v.w;
    }

    float4 r;
    r.x = fmaxf(acc.x, 0.f);
    r.y = fmaxf(acc.y, 0.f);
    r.z = fmaxf(acc.z, 0.f);
    r.w = fmaxf(acc.w, 0.f);
    reinterpret_cast<float4*>(out)[(size_t)node * 32 + lane] = r;
}

// ---------------------------------------------------------------------------
extern "C" void kernel_launch(void* const* d_in, const int* in_sizes, int n_in,
                              void* d_out, int out_size) {
    const float* feat = (const float*)d_in[0];   // [50000,128] f32
    const int*   src  = (const int*)d_in[1];     // [800000] i32
    const int*   dst  = (const int*)d_in[2];     // [800000] i32
    const float* W    = (const float*)d_in[3];   // [128,128] f32
    const float* bias = (const float*)d_in[4];   // [128] f32
    float*       out  = (float*)d_out;           // [50000,128] f32

    (void)in_sizes; (void)n_in; (void)out_size;

    cudaFuncSetAttribute(fused_kernel,
                         cudaFuncAttributeMaxDynamicSharedMemorySize, SMEM_TOTAL);

    hist_kernel<<<HIST_BLOCKS + WPREP_BLOCKS, 256>>>(dst, W);
    scan_local_kernel<<<SCAN_GRID, SCAN_BLK>>>();
    scan_add_kernel<<<SCAN_GRID, SCAN_BLK>>>();
    fused_kernel<<<FUSED_GRID, 256, SMEM_TOTAL>>>(src, dst, feat);

    {
        long long threads = (long long)N_NODES * 32;
        int blocks = (int)((threads + 255) / 256);
        gather_bias_relu_kernel<<<blocks, 256>>>(bias, out);
    }
}